// round 12
// baseline (speedup 1.0000x reference)
#include <cuda_runtime.h>
#include <cuda_bf16.h>
#include <cuda_fp16.h>
#include <cstdint>

#define Bb 32
#define Ss 128
#define Tt 128
#define DEMB 128
#define DENC 256
#define DDEC 512
#define Vv 32000

// ---------------- scratch (device globals; no runtime allocation) ----------------
__device__ float d_embS [Ss*Bb*DEMB];
__device__ float d_decin[Tt*Bb*DEMB];
__device__ float d_XGf  [Ss*Bb*4*DENC];
__device__ float d_XGb  [Ss*Bb*4*DENC];
__device__ float d_XGd  [Tt*Bb*4*DDEC];
__device__ float d_hf   [(Ss+1)*Bb*DENC];
__device__ float d_hb   [(Ss+1)*Bb*DENC];
__device__ float d_cf   [2*Bb*DENC];
__device__ float d_cb   [2*Bb*DENC];
__device__ float d_mem  [Bb*Ss*2*DENC];
__device__ float d_ccat [Bb*2*DENC];
__device__ float d_H    [(Tt+1)*Bb*DDEC];
__device__ float d_cd   [2*Bb*DDEC];
__device__ float d_decpart[4*Bb*4*DDEC];       // used by ct path
__device__ float d_FFN  [Tt*Bb*2*DDEC];
__device__ float d_HID  [Tt*Bb*DDEC];
__device__ int   d_bar_e[Ss];                  // encoder step barriers
__device__ int   d_bar_d[Tt];                  // decoder step barriers
// fp16 operands for tensor-core F2
__device__ __half d_Wf16 [Vv*DDEC];
__device__ __half d_HIDH [Tt*Bb*DDEC];

// ---------------- helpers ----------------
__device__ __forceinline__ float lrelu_f(float x){ return x >= 0.f ? x : 0.1f*x; }
__device__ __forceinline__ float sigm_f (float x){ return 1.f/(1.f+__expf(-x)); }
__device__ __forceinline__ float tanh_f (float x){
    float ax = fabsf(x);
    float e  = __expf(-2.f*ax);
    float r  = (1.f-e)/(1.f+e);
    return x >= 0.f ? r : -r;
}
__device__ __forceinline__ unsigned long long dup2(float a){
    unsigned long long r;
    asm("mov.b64 %0, {%1, %1};" : "=l"(r) : "f"(a));
    return r;
}
__device__ __forceinline__ void fma2(unsigned long long &c, unsigned long long a, unsigned long long w){
    asm("fma.rn.f32x2 %0, %1, %2, %0;" : "+l"(c) : "l"(a), "l"(w));
}
union F4U { float4 f; unsigned long long u[2]; };
union U64F2 { unsigned long long u; float2 f; };

__device__ __forceinline__ uint32_t smem_u32(const void* p){
    uint32_t a; asm("{ .reg .u64 t; cvta.to.shared.u64 t, %1; cvt.u32.u64 %0, t; }" : "=r"(a) : "l"(p));
    return a;
}
__device__ __forceinline__ void cp16(uint32_t saddr, const void* gaddr){
    asm volatile("cp.async.cg.shared.global [%0], [%1], 16;" :: "r"(saddr), "l"(gaddr));
}
__device__ __forceinline__ void ldm_x4(uint32_t addr, uint32_t &r0, uint32_t &r1, uint32_t &r2, uint32_t &r3){
    asm volatile("ldmatrix.sync.aligned.m8n8.x4.shared.b16 {%0,%1,%2,%3}, [%4];"
                 : "=r"(r0), "=r"(r1), "=r"(r2), "=r"(r3) : "r"(addr));
}
__device__ __forceinline__ void mma16816h(float* c, uint32_t a0, uint32_t a1, uint32_t a2, uint32_t a3,
                                          uint32_t b0, uint32_t b1){
    asm volatile("mma.sync.aligned.m16n8k16.row.col.f32.f16.f16.f32 "
                 "{%0,%1,%2,%3}, {%4,%5,%6,%7}, {%8,%9}, {%0,%1,%2,%3};"
                 : "+f"(c[0]), "+f"(c[1]), "+f"(c[2]), "+f"(c[3])
                 : "r"(a0), "r"(a1), "r"(a2), "r"(a3), "r"(b0), "r"(b1));
}

// ---------------- prep kernels ----------------
__global__ void p_emb(const int* __restrict__ inp, const float* __restrict__ tok_emb){
    int idx = blockIdx.x*256 + threadIdx.x;
    int sb = idx >> 7, d = idx & 127;
    int s = sb >> 5, b = sb & 31;
    d_embS[idx] = tok_emb[inp[b*Ss + s]*DEMB + d];
}
__global__ void p_decin(const int* __restrict__ x, const float* __restrict__ tok_emb,
                        const float* __restrict__ start_emb){
    int idx = blockIdx.x*256 + threadIdx.x;
    int tb = idx >> 7, d = idx & 127;
    int t = tb >> 5, b = tb & 31;
    d_decin[idx] = (t == 0) ? start_emb[d] : tok_emb[x[b*Tt + (t-1)]*DEMB + d];
}
__global__ void p_init(const int* __restrict__ label_i, const int* __restrict__ label,
                       const float* __restrict__ enc_style_emb, const float* __restrict__ style_emb){
    int idx = blockIdx.x*256 + threadIdx.x;
    if (idx < 16384){
        int dir = idx >> 13, r = idx & 8191;
        int b = r >> 8, j = r & 255;
        float v = enc_style_emb[label_i[b]*(2*DENC) + dir*DENC + j];
        (dir ? d_hb : d_hf)[b*DENC + j] = v;
    } else if (idx < 32768){
        // (cell state now lives in registers; keep zeroing d_cf/d_cb buffer0 halves harmlessly)
        int r = idx - 16384;
        int dir = r >> 13; r &= 8191;
        (dir ? d_cb : d_cf)[r] = 0.f;
    } else if (idx < 49152){
        int r = idx - 32768;
        int b = r >> 9, j = r & 511;
        d_H[b*DDEC + j] = style_emb[label[b]*DDEC + j];
    } else if (idx < 49152 + 256){
        int r = idx - 49152;
        if (r < Ss) d_bar_e[r] = 0;
        else        d_bar_d[r - Ss] = 0;
    }
}
__global__ void conv_w16(const float* __restrict__ src, __half* __restrict__ dst, int n){
    int i = blockIdx.x*256 + threadIdx.x;
    if (i < n) dst[i] = __float2half_rn(src[i]);
}

// ---------------- fp32 GEMM (XG / F1): C = A @ W^T ----------------
__global__ void __launch_bounds__(256) gemm_nt(
    const float* __restrict__ A, const float* __restrict__ W, float* __restrict__ C,
    int M, int N, int K,
    const float* __restrict__ bias1, const float* __restrict__ bias2,
    int act, int remapA)
{
    __shared__ float As[8][128];
    __shared__ float Bs[8][128];
    int tid = threadIdx.x;
    int bm = blockIdx.y * 128, bn = blockIdx.x * 128;
    int lr = tid >> 1;
    int lc = (tid & 1) << 2;
    int arow = bm + lr;
    if (remapA) arow = ((Ss-1 - (arow >> 5)) << 5) | (arow & 31);
    const float* Aptr = A + arow*K + lc;
    const float* Wptr = W + (bn + lr)*K + lc;

    int m0 = (tid >> 4) << 3;
    int n0 = (tid & 15) << 3;
    unsigned long long acc[8][4];
#pragma unroll
    for (int i=0;i<8;i++)
#pragma unroll
        for (int j=0;j<4;j++) acc[i][j] = 0ull;

    for (int k0 = 0; k0 < K; k0 += 8){
        float4 a4 = *(const float4*)(Aptr + k0);
        float4 w4 = *(const float4*)(Wptr + k0);
        As[lc+0][lr]=a4.x; As[lc+1][lr]=a4.y; As[lc+2][lr]=a4.z; As[lc+3][lr]=a4.w;
        Bs[lc+0][lr]=w4.x; Bs[lc+1][lr]=w4.y; Bs[lc+2][lr]=w4.z; Bs[lc+3][lr]=w4.w;
        __syncthreads();
#pragma unroll
        for (int kk=0; kk<8; kk++){
            float4 a0 = *(const float4*)&As[kk][m0];
            float4 a1 = *(const float4*)&As[kk][m0+4];
            F4U ub0, ub1;
            ub0.f = *(const float4*)&Bs[kk][n0];
            ub1.f = *(const float4*)&Bs[kk][n0+4];
            unsigned long long w0=ub0.u[0], w1=ub0.u[1], w2=ub1.u[0], w3=ub1.u[1];
            float av[8] = {a0.x,a0.y,a0.z,a0.w,a1.x,a1.y,a1.z,a1.w};
#pragma unroll
            for (int i=0;i<8;i++){
                unsigned long long ad = dup2(av[i]);
                fma2(acc[i][0], ad, w0);
                fma2(acc[i][1], ad, w1);
                fma2(acc[i][2], ad, w2);
                fma2(acc[i][3], ad, w3);
            }
        }
        __syncthreads();
    }
#pragma unroll
    for (int i=0;i<8;i++){
        int mg = bm + m0 + i;
#pragma unroll
        for (int j=0;j<4;j++){
            U64F2 u; u.u = acc[i][j];
            float2 v = u.f;
            int ng = bn + n0 + 2*j;
            if (bias1){ v.x += bias1[ng]; v.y += bias1[ng+1]; }
            if (bias2){ v.x += bias2[ng]; v.y += bias2[ng+1]; }
            if (act){ v.x = lrelu_f(v.x); v.y = lrelu_f(v.y); }
            *(float2*)&C[mg*N + ng] = v;
        }
    }
}

// ---------------- mma.sync fp16 single-pass F2 GEMM ----------------
#define F2_NCHUNK 16
#define F2_ASTG   (128*40*2)
#define F2_BSTG   (256*40*2)
#define F2_STG    (F2_ASTG + F2_BSTG)
#define F2_SMEM   (3*F2_STG)
__global__ void __launch_bounds__(256) f2_mma(
    const __half* __restrict__ AH, const __half* __restrict__ Bg, float* __restrict__ out)
{
    extern __shared__ __half sm[];
    int tid = threadIdx.x;
    int wid = tid >> 5, lane = tid & 31;
    int warp_m = wid & 1, warp_n = wid >> 1;
    int bm = blockIdx.x * 128;
    int bn = blockIdx.y * 256;
    uint32_t sbase = smem_u32(sm);

    float acc[4][8][4];
#pragma unroll
    for (int i=0;i<4;i++)
#pragma unroll
        for (int j=0;j<8;j++)
#pragma unroll
            for (int q=0;q<4;q++) acc[i][j][q] = 0.f;

    auto load_chunk = [&](int c, int s){
        int k0 = c * 32;
        uint32_t base = sbase + (uint32_t)s * F2_STG;
#pragma unroll
        for (int q=0; q<2; q++){
            int i = q*256 + tid;
            int row = i >> 2, sg = i & 3;
            cp16(base + (uint32_t)(row*80 + sg*16), AH + (size_t)(bm + row)*DDEC + k0 + sg*8);
        }
#pragma unroll
        for (int q=0; q<4; q++){
            int i = q*256 + tid;
            int row = i >> 2, sg = i & 3;
            cp16(base + F2_ASTG + (uint32_t)(row*80 + sg*16),
                 Bg + (size_t)(bn + row)*DDEC + k0 + sg*8);
        }
        asm volatile("cp.async.commit_group;" ::: "memory");
    };

    load_chunk(0, 0);
    load_chunk(1, 1);

    int ld_s = 2, cs = 0;
    for (int c = 0; c < F2_NCHUNK; c++){
        if (c < F2_NCHUNK-1) asm volatile("cp.async.wait_group 1;" ::: "memory");
        else                 asm volatile("cp.async.wait_group 0;" ::: "memory");
        __syncthreads();
        if (c + 2 < F2_NCHUNK){
            load_chunk(c+2, ld_s);
            ld_s++; if (ld_s == 3) ld_s = 0;
        }
        uint32_t baseA = sbase + (uint32_t)cs * F2_STG;
        uint32_t baseB = baseA + F2_ASTG;
#pragma unroll
        for (int ks = 0; ks < 2; ks++){
            int kc = ks * 16;
            int g = lane >> 3, r = lane & 7;
            uint32_t af[4][4];
#pragma unroll
            for (int mt=0; mt<4; mt++){
                int row = warp_m*64 + mt*16 + (g & 1)*8 + r;
                int col = kc + (g >> 1)*8;
                ldm_x4(baseA + (uint32_t)(row*80 + col*2), af[mt][0], af[mt][1], af[mt][2], af[mt][3]);
            }
            uint32_t bf[8][2];
#pragma unroll
            for (int j=0; j<4; j++){
                int nrow = warp_n*64 + (j*2 + (g >> 1))*8 + r;
                int col = kc + (g & 1)*8;
                ldm_x4(baseB + (uint32_t)(nrow*80 + col*2),
                       bf[j*2][0], bf[j*2][1], bf[j*2+1][0], bf[j*2+1][1]);
            }
#pragma unroll
            for (int mt=0; mt<4; mt++)
#pragma unroll
                for (int nt=0; nt<8; nt++)
                    mma16816h(acc[mt][nt], af[mt][0], af[mt][1], af[mt][2], af[mt][3],
                              bf[nt][0], bf[nt][1]);
        }
        __syncthreads();
        cs++; if (cs == 3) cs = 0;
    }

#pragma unroll
    for (int mt=0; mt<4; mt++){
#pragma unroll
        for (int half=0; half<2; half++){
            int mg = bm + warp_m*64 + mt*16 + (lane >> 2) + half*8;
            int t = mg >> 5, b = mg & 31;
            float* dst = out + (size_t)(b*Tt + t)*Vv + bn + warp_n*64;
#pragma unroll
            for (int nt=0; nt<8; nt++){
                float2 v;
                v.x = acc[mt][nt][half*2+0];
                v.y = acc[mt][nt][half*2+1];
                *(float2*)&dst[nt*8 + 2*(lane & 3)] = v;
            }
        }
    }
}

// ---------------- persistent encoder recurrence ----------------
// grid 128 = dir(2) x slice(64); slice covers j0=slice*4 (4 j x 4 gates = 16 cols).
// Weights resident in SMEM for all 128 steps; c-state in registers; spin barrier per step.
__global__ void __launch_bounds__(128) enc_persist(
    const float* __restrict__ Whh_f, const float* __restrict__ Whh_b)
{
    extern __shared__ float dsm[];
    float (*Wp)[20]  = (float(*)[20])dsm;                 // [256][20]  (k-major, col c)
    float (*hsm)[36] = (float(*)[36])(dsm + 256*20);      // [256][36]  (k-major, b)
    float (*gsm)[36] = (float(*)[36])(dsm + 256*20 + 256*36);  // [16][36]

    int cta = blockIdx.x;
    int dir = cta >> 6;
    int slice = cta & 63;
    int j0 = slice * 4;
    const float* W  = dir ? Whh_b : Whh_f;
    float* hbuf     = dir ? d_hb  : d_hf;
    const float* XG = dir ? d_XGb : d_XGf;
    float* cfin     = dir ? d_cb  : d_cf;
    int tid = threadIdx.x;

    // load weight slice: 16 rows x 256 k -> Wp[k][c]
    for (int i = tid; i < 16*256; i += 128){
        int c = i >> 8, k = i & 255;
        int g = c >> 2, jj = c & 3;
        Wp[k][c] = W[(g*DENC + j0 + jj)*DENC + k];
    }
    int n  = tid >> 3;            // 0..15 (col)
    int b0 = (tid & 7) * 4;       // 4 consecutive b
    int bcell = tid & 31, jjc = tid >> 5;   // cell mapping
    float c_state = 0.f;
    __syncthreads();

    for (int t = 0; t < Ss; t++){
        // XG prefetch for cell
        const float* xgp = XG + (t*Bb + bcell)*(4*DENC) + j0 + jjc;
        float xg0 = xgp[0], xg1 = xgp[DENC], xg2 = xgp[2*DENC], xg3 = xgp[3*DENC];
        // load h_t transposed into hsm[k][b]
        {
            int b = tid & 31, kq = tid >> 5;
            const float* hp = hbuf + t*(Bb*DENC) + b*DENC;
#pragma unroll
            for (int q = 0; q < 16; q++){
                int k4 = kq*16 + q;
                float4 v = *(const float4*)(hp + k4*4);
                hsm[k4*4+0][b]=v.x; hsm[k4*4+1][b]=v.y; hsm[k4*4+2][b]=v.z; hsm[k4*4+3][b]=v.w;
            }
        }
        __syncthreads();
        // gemm: acc(b0..b0+3, n)
        U64F2 acc01, acc23;
        acc01.f = make_float2(0.f,0.f); acc23.f = make_float2(0.f,0.f);
#pragma unroll 4
        for (int k = 0; k < DENC; k++){
            F4U hv; hv.f = *(const float4*)&hsm[k][b0];
            unsigned long long w2 = dup2(Wp[k][n]);
            fma2(acc01.u, hv.u[0], w2);
            fma2(acc23.u, hv.u[1], w2);
        }
        {
            float4 o; o.x = acc01.f.x; o.y = acc01.f.y; o.z = acc23.f.x; o.w = acc23.f.y;
            *(float4*)&gsm[n][b0] = o;
        }
        __syncthreads();
        // cell for (bcell, j0+jjc)
        float g0 = xg0 + gsm[0*4+jjc][bcell];
        float g1 = xg1 + gsm[1*4+jjc][bcell];
        float g2 = xg2 + gsm[2*4+jjc][bcell];
        float g3 = xg3 + gsm[3*4+jjc][bcell];
        float i_ = sigm_f(g0), f_ = sigm_f(g1), gg = tanh_f(g2), o_ = sigm_f(g3);
        c_state = f_*c_state + i_*gg;
        float hn = o_*tanh_f(c_state);
        hbuf[(t+1)*(Bb*DENC) + bcell*DENC + j0 + jjc] = hn;
        if (t == Ss-1) cfin[bcell*DENC + j0 + jjc] = c_state;
        // step barrier
        if (t < Ss-1){
            __threadfence();
            __syncthreads();
            if (tid == 0){
                atomicAdd(&d_bar_e[t], 1);
                while (*(volatile int*)&d_bar_e[t] < 128) __nanosleep(64);
                __threadfence();
            }
            __syncthreads();
        }
    }
}

// ---------------- persistent decoder recurrence ----------------
// grid 128 slices; slice covers j0=cta*4 (4 j x 4 gates = 16 cols). K=512.
__global__ void __launch_bounds__(128) dec_persist(const float* __restrict__ Whh_d)
{
    extern __shared__ float dsm[];
    float (*Wp)[20]  = (float(*)[20])dsm;                  // [512][20]
    float (*hsm)[36] = (float(*)[36])(dsm + 512*20);       // [512][36]
    float (*gsm)[36] = (float(*)[36])(dsm + 512*20 + 512*36);  // [16][36]

    int cta = blockIdx.x;
    int j0 = cta * 4;
    int tid = threadIdx.x;

    for (int i = tid; i < 16*512; i += 128){
        int c = i >> 9, k = i & 511;
        int g = c >> 2, jj = c & 3;
        Wp[k][c] = Whh_d[(g*DDEC + j0 + jj)*DDEC + k];
    }
    int n  = tid >> 3;
    int b0 = (tid & 7) * 4;
    int bcell = tid & 31, jjc = tid >> 5;
    float c_state;
    c_state = d_cd[bcell*DDEC + j0 + jjc];
    __syncthreads();

    for (int t = 0; t < Tt; t++){
        const float* xgp = d_XGd + (t*Bb + bcell)*(4*DDEC) + j0 + jjc;
        float xg0 = xgp[0], xg1 = xgp[DDEC], xg2 = xgp[2*DDEC], xg3 = xgp[3*DDEC];
        {
            int b = tid & 31, kq = tid >> 5;
            const float* hp = d_H + t*(Bb*DDEC) + b*DDEC;
#pragma unroll
            for (int q = 0; q < 32; q++){
                int k4 = kq*32 + q;
                float4 v = *(const float4*)(hp + k4*4);
                hsm[k4*4+0][b]=v.x; hsm[k4*4+1][b]=v.y; hsm[k4*4+2][b]=v.z; hsm[k4*4+3][b]=v.w;
            }
        }
        __syncthreads();
        U64F2 acc01, acc23;
        acc01.f = make_float2(0.f,0.f); acc23.f = make_float2(0.f,0.f);
#pragma unroll 4
        for (int k = 0; k < DDEC; k++){
            F4U hv; hv.f = *(const float4*)&hsm[k][b0];
            unsigned long long w2 = dup2(Wp[k][n]);
            fma2(acc01.u, hv.u[0], w2);
            fma2(acc23.u, hv.u[1], w2);
        }
        {
            float4 o; o.x = acc01.f.x; o.y = acc01.f.y; o.z = acc23.f.x; o.w = acc23.f.y;
            *(float4*)&gsm[n][b0] = o;
        }
        __syncthreads();
        float g0 = xg0 + gsm[0*4+jjc][bcell];
        float g1 = xg1 + gsm[1*4+jjc][bcell];
        float g2 = xg2 + gsm[2*4+jjc][bcell];
        float g3 = xg3 + gsm[3*4+jjc][bcell];
        float i_ = sigm_f(g0), f_ = sigm_f(g1), gg = tanh_f(g2), o_ = sigm_f(g3);
        c_state = f_*c_state + i_*gg;
        float hn = o_*tanh_f(c_state);
        d_H[(t+1)*(Bb*DDEC) + bcell*DDEC + j0 + jjc] = hn;
        if (t < Tt-1){
            __threadfence();
            __syncthreads();
            if (tid == 0){
                atomicAdd(&d_bar_d[t], 1);
                while (*(volatile int*)&d_bar_d[t] < 128) __nanosleep(64);
                __threadfence();
            }
            __syncthreads();
        }
    }
}

// ---------------- small-M GEMM (ct path) ----------------
__global__ void __launch_bounds__(128) lstm_hgemm(
    const float* __restrict__ H0, const float* __restrict__ W0,
    float* __restrict__ part, int Ntot, int KH, int KS)
{
    int n0blk = blockIdx.x * 64;
    int ksub = KH / KS;
    int kbase = blockIdx.y * ksub;
    __shared__ float As[32][36];
    __shared__ float Ws[32][68];
    int tid = threadIdx.x;
    int bth = (tid >> 4) << 2;
    int nth = (tid & 15) << 2;
    float acc[4][4];
#pragma unroll
    for (int i=0;i<4;i++)
#pragma unroll
        for (int j=0;j<4;j++) acc[i][j] = 0.f;

    for (int k0 = 0; k0 < ksub; k0 += 32){
#pragma unroll
        for (int q=0;q<2;q++){
            int f4 = tid*2 + q;
            int bb = f4 >> 3, kq = (f4 & 7) << 2;
            float4 v = *(const float4*)(H0 + bb*KH + kbase + k0 + kq);
            As[kq+0][bb]=v.x; As[kq+1][bb]=v.y; As[kq+2][bb]=v.z; As[kq+3][bb]=v.w;
        }
#pragma unroll
        for (int q=0;q<4;q++){
            int f4 = tid*4 + q;
            int nn = f4 >> 3, kq = (f4 & 7) << 2;
            float4 v = *(const float4*)(W0 + (n0blk+nn)*KH + kbase + k0 + kq);
            Ws[kq+0][nn]=v.x; Ws[kq+1][nn]=v.y; Ws[kq+2][nn]=v.z; Ws[kq+3][nn]=v.w;
        }
        __syncthreads();
#pragma unroll
        for (int kk=0; kk<32; kk++){
            float4 a4 = *(const float4*)&As[kk][bth];
            float4 w4 = *(const float4*)&Ws[kk][nth];
            float aa[4] = {a4.x,a4.y,a4.z,a4.w};
            float ww[4] = {w4.x,w4.y,w4.z,w4.w};
#pragma unroll
            for (int i=0;i<4;i++)
#pragma unroll
                for (int j=0;j<4;j++) acc[i][j] += aa[i]*ww[j];
        }
        __syncthreads();
    }
    float* pbase = part + (blockIdx.y*32)*Ntot;
#pragma unroll
    for (int i=0;i<4;i++){
        float4 v; v.x=acc[i][0]; v.y=acc[i][1]; v.z=acc[i][2]; v.w=acc[i][3];
        *(float4*)&pbase[(bth+i)*Ntot + n0blk + nth] = v;
    }
}

// ---------------- misc glue ----------------
__global__ void mem_assemble(){
    int idx = blockIdx.x*256 + threadIdx.x;
    int b = idx >> 16, r = idx & 65535;
    int s = r >> 9, d = r & 511;
    float v;
    if (d < DENC) v = d_hf[((s+1)*Bb + b)*DENC + d];
    else          v = d_hb[((Ss - s)*Bb + b)*DENC + (d - DENC)];
    d_mem[idx] = v;
}
__global__ void ccat_build(){
    int idx = blockIdx.x*256 + threadIdx.x;
    int b = idx >> 9, j = idx & 511;
    d_ccat[idx] = (j < DENC) ? d_cf[b*DENC + j] : d_cb[b*DENC + (j - DENC)];
}
__global__ void ct_combine(){
    int idx = blockIdx.x*256 + threadIdx.x;
    int b = idx >> 9, j = idx & 511;
    float v = 0.f;
#pragma unroll
    for (int ky=0; ky<4; ky++) v += d_decpart[(ky*Bb + b)*DDEC + j];
    d_cd[b*DDEC + j] = lrelu_f(v);
}

// ---------------- attention ----------------
__global__ void __launch_bounds__(256) attn_kernel(){
    int b  = blockIdx.x;
    int t0 = blockIdx.y * 8;
    __shared__ float hs[8][512];
    __shared__ float sc[8][128];
    int tid = threadIdx.x;
    for (int i = tid; i < 8*512; i += 256){
        int tt = i >> 9, d = i & 511;
        hs[tt][d] = d_H[((t0 + tt + 1)*Bb + b)*DDEC + d];
    }
    __syncthreads();
    int w = tid >> 5, lane = tid & 31;
    const float scale = 0.04419417382415922f;
    for (int si = 0; si < 16; si++){
        int s = w*16 + si;
        const float* mrow = d_mem + (b*Ss + s)*DDEC;
        float acc[8] = {0,0,0,0,0,0,0,0};
#pragma unroll
        for (int q=0; q<4; q++){
            int d = q*128 + lane*4;
            float4 m4 = *(const float4*)(mrow + d);
#pragma unroll
            for (int tt=0; tt<8; tt++){
                float4 h4 = *(const float4*)&hs[tt][d];
                acc[tt] += m4.x*h4.x + m4.y*h4.y + m4.z*h4.z + m4.w*h4.w;
            }
        }
#pragma unroll
        for (int tt=0; tt<8; tt++){
            float v = acc[tt];
#pragma unroll
            for (int o=16;o>0;o>>=1) v += __shfl_xor_sync(0xffffffffu, v, o);
            if (lane == 0) sc[tt][s] = v * scale;
        }
    }
    __syncthreads();
    {
        int tt = w;
        float vals[4], m = -1e30f;
#pragma unroll
        for (int q=0;q<4;q++){ vals[q] = sc[tt][lane + q*32]; m = fmaxf(m, vals[q]); }
#pragma unroll
        for (int o=16;o>0;o>>=1) m = fmaxf(m, __shfl_xor_sync(0xffffffffu, m, o));
        float ssum = 0.f;
#pragma unroll
        for (int q=0;q<4;q++){ vals[q] = __expf(vals[q]-m); ssum += vals[q]; }
#pragma unroll
        for (int o=16;o>0;o>>=1) ssum += __shfl_xor_sync(0xffffffffu, ssum, o);
        float inv = 1.f/ssum;
#pragma unroll
        for (int q=0;q<4;q++) sc[tt][lane + q*32] = vals[q]*inv;
    }
    __syncthreads();
    {
        int d0 = tid*2;
        float acc[8][2];
#pragma unroll
        for (int tt=0;tt<8;tt++){ acc[tt][0]=0.f; acc[tt][1]=0.f; }
        for (int s=0; s<Ss; s++){
            float2 m2 = *(const float2*)(d_mem + (b*Ss + s)*DDEC + d0);
#pragma unroll
            for (int tt=0;tt<8;tt++){
                float p = sc[tt][s];
                acc[tt][0] += p*m2.x; acc[tt][1] += p*m2.y;
            }
        }
#pragma unroll
        for (int tt=0;tt<8;tt++){
            int rr = (t0+tt)*Bb + b;
            float2 v; v.x = acc[tt][0]; v.y = acc[tt][1];
            *(float2*)&d_FFN[rr*(2*DDEC) + DDEC + d0] = v;
        }
    }
    for (int i = tid; i < 8*512; i += 256){
        int tt = i >> 9, d = i & 511;
        int rr = (t0+tt)*Bb + b;
        d_FFN[rr*(2*DDEC) + d] = hs[tt][d];
    }
}

// ---------------- launcher ----------------
extern "C" void kernel_launch(void* const* d_in, const int* in_sizes, int n_in,
                              void* d_out, int out_size)
{
    const int*   inp        = (const int*)  d_in[0];
    const int*   label_i    = (const int*)  d_in[1];
    const int*   x          = (const int*)  d_in[2];
    const int*   label      = (const int*)  d_in[3];
    const float* start_emb  = (const float*)d_in[4];
    const float* tok_emb    = (const float*)d_in[5];
    const float* enc_style  = (const float*)d_in[6];
    const float* style_emb  = (const float*)d_in[7];
    const float* Wih_f      = (const float*)d_in[8];
    const float* Whh_f      = (const float*)d_in[9];
    const float* bih_f      = (const float*)d_in[10];
    const float* bhh_f      = (const float*)d_in[11];
    const float* Wih_b      = (const float*)d_in[12];
    const float* Whh_b      = (const float*)d_in[13];
    const float* bih_b      = (const float*)d_in[14];
    const float* bhh_b      = (const float*)d_in[15];
    const float* Wih_d      = (const float*)d_in[16];
    const float* Whh_d      = (const float*)d_in[17];
    const float* bih_d      = (const float*)d_in[18];
    const float* bhh_d      = (const float*)d_in[19];
    const float* W_tr       = (const float*)d_in[20];
    const float* W_f1       = (const float*)d_in[21];
    const float* b_f1       = (const float*)d_in[22];
    const float* W_f2       = (const float*)d_in[23];
    float* out = (float*)d_out;

    float *embS, *decin, *XGf, *XGb, *XGd, *ccat, *decpart, *FFN, *HID;
    __half *Wf16, *HIDH;
    cudaGetSymbolAddress((void**)&embS,   d_embS);
    cudaGetSymbolAddress((void**)&decin,  d_decin);
    cudaGetSymbolAddress((void**)&XGf,    d_XGf);
    cudaGetSymbolAddress((void**)&XGb,    d_XGb);
    cudaGetSymbolAddress((void**)&XGd,    d_XGd);
    cudaGetSymbolAddress((void**)&ccat,   d_ccat);
    cudaGetSymbolAddress((void**)&decpart,d_decpart);
    cudaGetSymbolAddress((void**)&FFN,    d_FFN);
    cudaGetSymbolAddress((void**)&HID,    d_HID);
    cudaGetSymbolAddress((void**)&Wf16,   d_Wf16);
    cudaGetSymbolAddress((void**)&HIDH,   d_HIDH);

    const int ENC_SMEM = (256*20 + 256*36 + 16*36) * 4;   // ~59.9 KB
    const int DEC_SMEM = (512*20 + 512*36 + 16*36) * 4;   // ~117.0 KB
    cudaFuncSetAttribute(f2_mma,      cudaFuncAttributeMaxDynamicSharedMemorySize, F2_SMEM);
    cudaFuncSetAttribute(enc_persist, cudaFuncAttributeMaxDynamicSharedMemorySize, ENC_SMEM);
    cudaFuncSetAttribute(dec_persist, cudaFuncAttributeMaxDynamicSharedMemorySize, DEC_SMEM);

    // prep
    p_emb  <<<2048,256>>>(inp, tok_emb);
    p_decin<<<2048,256>>>(x, tok_emb, start_emb);
    p_init <<<194,256>>>(label_i, label, enc_style, style_emb);
    conv_w16<<<64000,256>>>(W_f2, Wf16, Vv*DDEC);

    // batched x-part of all LSTM gates (biases folded in)
    gemm_nt<<<dim3( 8,32),256>>>(embS,  Wih_f, XGf, 4096,1024, 128, bih_f, bhh_f, 0,0);
    gemm_nt<<<dim3( 8,32),256>>>(embS,  Wih_b, XGb, 4096,1024, 128, bih_b, bhh_b, 0,1);
    gemm_nt<<<dim3(16,32),256>>>(decin, Wih_d, XGd, 4096,2048, 128, bih_d, bhh_d, 0,0);

    // encoder recurrence: ONE persistent kernel (128 co-resident CTAs, spin barriers)
    enc_persist<<<128,128,ENC_SMEM>>>(Whh_f, Whh_b);
    mem_assemble<<<8192,256>>>();

    // c_t = lrelu(concat(cf,cb) @ W_tr^T)
    ccat_build<<<64,256>>>();
    lstm_hgemm<<<dim3(8,4),128>>>(ccat, W_tr, decpart, DDEC, DDEC, 4);
    ct_combine<<<64,256>>>();

    // decoder recurrence: ONE persistent kernel
    dec_persist<<<128,128,DEC_SMEM>>>(Whh_d);

    // batched attention -> FFN input
    attn_kernel<<<dim3(32,16),256>>>();

    // F1: lrelu(FFN @ W_f1^T + b_f1)
    gemm_nt<<<dim3(4,32),256>>>(FFN, W_f1, HID, 4096, 512, 1024, b_f1, nullptr, 1,0);
    conv_w16<<<8192,256>>>(HID, HIDH, Tt*Bb*DDEC);

    // F2 on tensor cores: single-pass fp16, remapped to [B,T,V]
    f2_mma<<<dim3(32,125), 256, F2_SMEM>>>(HIDH, Wf16, out);
}

// round 13
// speedup vs baseline: 1.2002x; 1.2002x over previous
#include <cuda_runtime.h>
#include <cuda_bf16.h>
#include <cuda_fp16.h>
#include <cstdint>

#define Bb 32
#define Ss 128
#define Tt 128
#define DEMB 128
#define DENC 256
#define DDEC 512
#define Vv 32000

// ---------------- scratch (device globals; no runtime allocation) ----------------
__device__ float d_embS [Ss*Bb*DEMB];
__device__ float d_decin[Tt*Bb*DEMB];
__device__ float d_XGf  [Ss*Bb*4*DENC];
__device__ float d_XGb  [Ss*Bb*4*DENC];
__device__ float d_XGd  [Tt*Bb*4*DDEC];
__device__ float d_hf   [(Ss+1)*Bb*DENC];
__device__ float d_hb   [(Ss+1)*Bb*DENC];
__device__ float d_cf   [2*Bb*DENC];
__device__ float d_cb   [2*Bb*DENC];
__device__ float d_mem  [Bb*Ss*2*DENC];
__device__ float d_ccat [Bb*2*DENC];
__device__ float d_H    [(Tt+1)*Bb*DDEC];
__device__ float d_cd   [2*Bb*DDEC];
__device__ float d_decpart[4*Bb*4*DDEC];       // ct path scratch
__device__ float d_FFN  [Tt*Bb*2*DDEC];
__device__ float d_HID  [Tt*Bb*DDEC];
// fp16 operands for tensor-core F2
__device__ __half d_Wf16 [Vv*DDEC];
__device__ __half d_HIDH [Tt*Bb*DDEC];

// ---------------- helpers ----------------
__device__ __forceinline__ float lrelu_f(float x){ return x >= 0.f ? x : 0.1f*x; }
__device__ __forceinline__ float sigm_f (float x){ return 1.f/(1.f+__expf(-x)); }
__device__ __forceinline__ float tanh_f (float x){
    float ax = fabsf(x);
    float e  = __expf(-2.f*ax);
    float r  = (1.f-e)/(1.f+e);
    return x >= 0.f ? r : -r;
}
__device__ __forceinline__ unsigned long long dup2(float a){
    unsigned long long r;
    asm("mov.b64 %0, {%1, %1};" : "=l"(r) : "f"(a));
    return r;
}
__device__ __forceinline__ void fma2(unsigned long long &c, unsigned long long a, unsigned long long w){
    asm("fma.rn.f32x2 %0, %1, %2, %0;" : "+l"(c) : "l"(a), "l"(w));
}
union F4U { float4 f; unsigned long long u[2]; };
union U64F2 { unsigned long long u; float2 f; };

__device__ __forceinline__ uint32_t smem_u32(const void* p){
    uint32_t a; asm("{ .reg .u64 t; cvta.to.shared.u64 t, %1; cvt.u32.u64 %0, t; }" : "=r"(a) : "l"(p));
    return a;
}
__device__ __forceinline__ void cp16(uint32_t saddr, const void* gaddr){
    asm volatile("cp.async.cg.shared.global [%0], [%1], 16;" :: "r"(saddr), "l"(gaddr));
}
__device__ __forceinline__ void ldm_x4(uint32_t addr, uint32_t &r0, uint32_t &r1, uint32_t &r2, uint32_t &r3){
    asm volatile("ldmatrix.sync.aligned.m8n8.x4.shared.b16 {%0,%1,%2,%3}, [%4];"
                 : "=r"(r0), "=r"(r1), "=r"(r2), "=r"(r3) : "r"(addr));
}
__device__ __forceinline__ void mma16816h(float* c, uint32_t a0, uint32_t a1, uint32_t a2, uint32_t a3,
                                          uint32_t b0, uint32_t b1){
    asm volatile("mma.sync.aligned.m16n8k16.row.col.f32.f16.f16.f32 "
                 "{%0,%1,%2,%3}, {%4,%5,%6,%7}, {%8,%9}, {%0,%1,%2,%3};"
                 : "+f"(c[0]), "+f"(c[1]), "+f"(c[2]), "+f"(c[3])
                 : "r"(a0), "r"(a1), "r"(a2), "r"(a3), "r"(b0), "r"(b1));
}

// ---------------- prep kernels ----------------
__global__ void p_emb(const int* __restrict__ inp, const float* __restrict__ tok_emb){
    int idx = blockIdx.x*256 + threadIdx.x;
    int sb = idx >> 7, d = idx & 127;
    int s = sb >> 5, b = sb & 31;
    d_embS[idx] = tok_emb[inp[b*Ss + s]*DEMB + d];
}
__global__ void p_decin(const int* __restrict__ x, const float* __restrict__ tok_emb,
                        const float* __restrict__ start_emb){
    int idx = blockIdx.x*256 + threadIdx.x;
    int tb = idx >> 7, d = idx & 127;
    int t = tb >> 5, b = tb & 31;
    d_decin[idx] = (t == 0) ? start_emb[d] : tok_emb[x[b*Tt + (t-1)]*DEMB + d];
}
__global__ void p_init(const int* __restrict__ label_i, const int* __restrict__ label,
                       const float* __restrict__ enc_style_emb, const float* __restrict__ style_emb){
    int idx = blockIdx.x*256 + threadIdx.x;
    if (idx < 16384){
        int dir = idx >> 13, r = idx & 8191;
        int b = r >> 8, j = r & 255;
        float v = enc_style_emb[label_i[b]*(2*DENC) + dir*DENC + j];
        (dir ? d_hb : d_hf)[b*DENC + j] = v;
    } else if (idx < 32768){
        int r = idx - 16384;
        int dir = r >> 13; r &= 8191;
        (dir ? d_cb : d_cf)[r] = 0.f;       // ping-pong buffer 0 = c0
    } else {
        int r = idx - 32768;
        int b = r >> 9, j = r & 511;
        d_H[b*DDEC + j] = style_emb[label[b]*DDEC + j];
    }
}
__global__ void conv_w16(const float* __restrict__ src, __half* __restrict__ dst, int n){
    int i = blockIdx.x*256 + threadIdx.x;
    if (i < n) dst[i] = __float2half_rn(src[i]);
}

// ---------------- fp32 GEMM (XG / F1): C = A @ W^T ----------------
__global__ void __launch_bounds__(256) gemm_nt(
    const float* __restrict__ A, const float* __restrict__ W, float* __restrict__ C,
    int M, int N, int K,
    const float* __restrict__ bias1, const float* __restrict__ bias2,
    int act, int remapA)
{
    __shared__ float As[8][128];
    __shared__ float Bs[8][128];
    int tid = threadIdx.x;
    int bm = blockIdx.y * 128, bn = blockIdx.x * 128;
    int lr = tid >> 1;
    int lc = (tid & 1) << 2;
    int arow = bm + lr;
    if (remapA) arow = ((Ss-1 - (arow >> 5)) << 5) | (arow & 31);
    const float* Aptr = A + arow*K + lc;
    const float* Wptr = W + (bn + lr)*K + lc;

    int m0 = (tid >> 4) << 3;
    int n0 = (tid & 15) << 3;
    unsigned long long acc[8][4];
#pragma unroll
    for (int i=0;i<8;i++)
#pragma unroll
        for (int j=0;j<4;j++) acc[i][j] = 0ull;

    for (int k0 = 0; k0 < K; k0 += 8){
        float4 a4 = *(const float4*)(Aptr + k0);
        float4 w4 = *(const float4*)(Wptr + k0);
        As[lc+0][lr]=a4.x; As[lc+1][lr]=a4.y; As[lc+2][lr]=a4.z; As[lc+3][lr]=a4.w;
        Bs[lc+0][lr]=w4.x; Bs[lc+1][lr]=w4.y; Bs[lc+2][lr]=w4.z; Bs[lc+3][lr]=w4.w;
        __syncthreads();
#pragma unroll
        for (int kk=0; kk<8; kk++){
            float4 a0 = *(const float4*)&As[kk][m0];
            float4 a1 = *(const float4*)&As[kk][m0+4];
            F4U ub0, ub1;
            ub0.f = *(const float4*)&Bs[kk][n0];
            ub1.f = *(const float4*)&Bs[kk][n0+4];
            unsigned long long w0=ub0.u[0], w1=ub0.u[1], w2=ub1.u[0], w3=ub1.u[1];
            float av[8] = {a0.x,a0.y,a0.z,a0.w,a1.x,a1.y,a1.z,a1.w};
#pragma unroll
            for (int i=0;i<8;i++){
                unsigned long long ad = dup2(av[i]);
                fma2(acc[i][0], ad, w0);
                fma2(acc[i][1], ad, w1);
                fma2(acc[i][2], ad, w2);
                fma2(acc[i][3], ad, w3);
            }
        }
        __syncthreads();
    }
#pragma unroll
    for (int i=0;i<8;i++){
        int mg = bm + m0 + i;
#pragma unroll
        for (int j=0;j<4;j++){
            U64F2 u; u.u = acc[i][j];
            float2 v = u.f;
            int ng = bn + n0 + 2*j;
            if (bias1){ v.x += bias1[ng]; v.y += bias1[ng+1]; }
            if (bias2){ v.x += bias2[ng]; v.y += bias2[ng+1]; }
            if (act){ v.x = lrelu_f(v.x); v.y = lrelu_f(v.y); }
            *(float2*)&C[mg*N + ng] = v;
        }
    }
}

// ---------------- mma.sync fp16 single-pass F2 GEMM ----------------
#define F2_NCHUNK 16
#define F2_ASTG   (128*40*2)
#define F2_BSTG   (256*40*2)
#define F2_STG    (F2_ASTG + F2_BSTG)
#define F2_SMEM   (3*F2_STG)
__global__ void __launch_bounds__(256) f2_mma(
    const __half* __restrict__ AH, const __half* __restrict__ Bg, float* __restrict__ out)
{
    extern __shared__ __half sm[];
    int tid = threadIdx.x;
    int wid = tid >> 5, lane = tid & 31;
    int warp_m = wid & 1, warp_n = wid >> 1;
    int bm = blockIdx.x * 128;
    int bn = blockIdx.y * 256;
    uint32_t sbase = smem_u32(sm);

    float acc[4][8][4];
#pragma unroll
    for (int i=0;i<4;i++)
#pragma unroll
        for (int j=0;j<8;j++)
#pragma unroll
            for (int q=0;q<4;q++) acc[i][j][q] = 0.f;

    auto load_chunk = [&](int c, int s){
        int k0 = c * 32;
        uint32_t base = sbase + (uint32_t)s * F2_STG;
#pragma unroll
        for (int q=0; q<2; q++){
            int i = q*256 + tid;
            int row = i >> 2, sg = i & 3;
            cp16(base + (uint32_t)(row*80 + sg*16), AH + (size_t)(bm + row)*DDEC + k0 + sg*8);
        }
#pragma unroll
        for (int q=0; q<4; q++){
            int i = q*256 + tid;
            int row = i >> 2, sg = i & 3;
            cp16(base + F2_ASTG + (uint32_t)(row*80 + sg*16),
                 Bg + (size_t)(bn + row)*DDEC + k0 + sg*8);
        }
        asm volatile("cp.async.commit_group;" ::: "memory");
    };

    load_chunk(0, 0);
    load_chunk(1, 1);

    int ld_s = 2, cs = 0;
    for (int c = 0; c < F2_NCHUNK; c++){
        if (c < F2_NCHUNK-1) asm volatile("cp.async.wait_group 1;" ::: "memory");
        else                 asm volatile("cp.async.wait_group 0;" ::: "memory");
        __syncthreads();
        if (c + 2 < F2_NCHUNK){
            load_chunk(c+2, ld_s);
            ld_s++; if (ld_s == 3) ld_s = 0;
        }
        uint32_t baseA = sbase + (uint32_t)cs * F2_STG;
        uint32_t baseB = baseA + F2_ASTG;
#pragma unroll
        for (int ks = 0; ks < 2; ks++){
            int kc = ks * 16;
            int g = lane >> 3, r = lane & 7;
            uint32_t af[4][4];
#pragma unroll
            for (int mt=0; mt<4; mt++){
                int row = warp_m*64 + mt*16 + (g & 1)*8 + r;
                int col = kc + (g >> 1)*8;
                ldm_x4(baseA + (uint32_t)(row*80 + col*2), af[mt][0], af[mt][1], af[mt][2], af[mt][3]);
            }
            uint32_t bf[8][2];
#pragma unroll
            for (int j=0; j<4; j++){
                int nrow = warp_n*64 + (j*2 + (g >> 1))*8 + r;
                int col = kc + (g & 1)*8;
                ldm_x4(baseB + (uint32_t)(nrow*80 + col*2),
                       bf[j*2][0], bf[j*2][1], bf[j*2+1][0], bf[j*2+1][1]);
            }
#pragma unroll
            for (int mt=0; mt<4; mt++)
#pragma unroll
                for (int nt=0; nt<8; nt++)
                    mma16816h(acc[mt][nt], af[mt][0], af[mt][1], af[mt][2], af[mt][3],
                              bf[nt][0], bf[nt][1]);
        }
        __syncthreads();
        cs++; if (cs == 3) cs = 0;
    }

#pragma unroll
    for (int mt=0; mt<4; mt++){
#pragma unroll
        for (int half=0; half<2; half++){
            int mg = bm + warp_m*64 + mt*16 + (lane >> 2) + half*8;
            int t = mg >> 5, b = mg & 31;
            float* dst = out + (size_t)(b*Tt + t)*Vv + bn + warp_n*64;
#pragma unroll
            for (int nt=0; nt<8; nt++){
                float2 v;
                v.x = acc[mt][nt][half*2+0];
                v.y = acc[mt][nt][half*2+1];
                *(float2*)&dst[nt*8 + 2*(lane & 3)] = v;
            }
        }
    }
}

// ---------------- fused full-K encoder step (GEMM + cell, one kernel, no atomics) ----
// grid (64, 2): j0 = bx*4 (4 j x 4 gates = 16 cols), dir = by. 128 thr, 4 out/thread.
#define ENC2_SMEM ((256*17 + 256*32 + 16*36)*4)
__global__ void __launch_bounds__(128) enc_step(
    const float* __restrict__ Whh_f, const float* __restrict__ Whh_b, int t)
{
    extern __shared__ float esm[];
    float* Wsm = esm;                  // [256][17]
    float* hsm = esm + 256*17;         // [256][32] XOR-swizzled b-groups
    float* gsm = esm + 256*17 + 256*32;// [16][36]
    int tid = threadIdx.x;
    int j0 = blockIdx.x * 4;
    int dir = blockIdx.y;
    const float* W  = dir ? Whh_b : Whh_f;
    const float* XG = dir ? d_XGb : d_XGf;
    float* hbuf = dir ? d_hb : d_hf;
    float* cbuf = dir ? d_cb : d_cf;

    // stage W slice: 16 cols (c = g*4+jj) x 256 k, coalesced reads
#pragma unroll
    for (int q = 0; q < 32; q++){
        int i = tid + q*128;
        int k = i & 255, c = i >> 8;
        Wsm[k*17 + c] = W[((c>>2)*DENC + j0 + (c&3))*DENC + k];
    }
    // stage h_t transposed + swizzled: element (k=4k4+j, b) -> hsm[k][colgrp^swz]
    const float* hg = hbuf + t*Bb*DENC;
#pragma unroll
    for (int q = 0; q < 16; q++){
        int i = tid + q*128;
        int b = i >> 6, k4 = i & 63;
        float4 v = *(const float4*)(hg + b*DENC + k4*4);
        int col = (((b>>2) ^ (k4 & 7)) << 2) + (b & 3);
        hsm[(4*k4+0)*32 + col] = v.x;
        hsm[(4*k4+1)*32 + col] = v.y;
        hsm[(4*k4+2)*32 + col] = v.z;
        hsm[(4*k4+3)*32 + col] = v.w;
    }
    __syncthreads();

    // GEMM: out(b0..b0+3, n), n = tid&15, b0 = (tid>>4)*4
    int n = tid & 15;
    int bg = tid >> 4;                 // b-group 0..7
    U64F2 a01, a23, b01, b23;
    a01.u = 0ull; a23.u = 0ull; b01.u = 0ull; b23.u = 0ull;
#pragma unroll 4
    for (int k4 = 0; k4 < 64; k4++){
        int colg = ((bg ^ (k4 & 7)) << 2);
        const float* hrow = hsm + 4*k4*32 + colg;
        const float* wrow = Wsm + 4*k4*17 + n;
        F4U h0; h0.f = *(const float4*)(hrow);
        unsigned long long w0 = dup2(wrow[0]);
        fma2(a01.u, h0.u[0], w0); fma2(a23.u, h0.u[1], w0);
        F4U h1; h1.f = *(const float4*)(hrow + 32);
        unsigned long long w1 = dup2(wrow[17]);
        fma2(b01.u, h1.u[0], w1); fma2(b23.u, h1.u[1], w1);
        F4U h2; h2.f = *(const float4*)(hrow + 64);
        unsigned long long w2 = dup2(wrow[34]);
        fma2(a01.u, h2.u[0], w2); fma2(a23.u, h2.u[1], w2);
        F4U h3; h3.f = *(const float4*)(hrow + 96);
        unsigned long long w3 = dup2(wrow[51]);
        fma2(b01.u, h3.u[0], w3); fma2(b23.u, h3.u[1], w3);
    }
    {
        float4 o;
        o.x = a01.f.x + b01.f.x; o.y = a01.f.y + b01.f.y;
        o.z = a23.f.x + b23.f.x; o.w = a23.f.y + b23.f.y;
        *(float4*)&gsm[n*36 + bg*4] = o;
    }
    __syncthreads();

    // cell: 4 j x 32 b = 128 cells, one per thread
    int b = tid & 31, jj = tid >> 5;
    const float* xgp = XG + (t*Bb + b)*(4*DENC) + j0 + jj;
    float g0 = xgp[0]      + gsm[(0*4+jj)*36 + b];
    float g1 = xgp[DENC]   + gsm[(1*4+jj)*36 + b];
    float g2 = xgp[2*DENC] + gsm[(2*4+jj)*36 + b];
    float g3 = xgp[3*DENC] + gsm[(3*4+jj)*36 + b];
    float cold = cbuf[(t&1)*Bb*DENC + b*DENC + j0 + jj];
    float i_ = sigm_f(g0), f_ = sigm_f(g1), gg = tanh_f(g2), o_ = sigm_f(g3);
    float cn = f_*cold + i_*gg;
    float hn = o_*tanh_f(cn);
    cbuf[((t+1)&1)*Bb*DENC + b*DENC + j0 + jj] = cn;
    hbuf[(t+1)*Bb*DENC + b*DENC + j0 + jj] = hn;
}

// ---------------- fused full-K decoder step ----------------
// grid 128: j0 = bx*4 (4 j x 4 gates = 16 cols). K=512.
#define DEC2_SMEM ((512*17 + 512*32 + 16*36)*4)
__global__ void __launch_bounds__(128) dec_step(const float* __restrict__ Whh_d, int t)
{
    extern __shared__ float dsm2[];
    float* Wsm = dsm2;                   // [512][17]
    float* hsm = dsm2 + 512*17;          // [512][32]
    float* gsm = dsm2 + 512*17 + 512*32; // [16][36]
    int tid = threadIdx.x;
    int j0 = blockIdx.x * 4;

#pragma unroll
    for (int q = 0; q < 64; q++){
        int i = tid + q*128;
        int k = i & 511, c = i >> 9;
        Wsm[k*17 + c] = Whh_d[((c>>2)*DDEC + j0 + (c&3))*DDEC + k];
    }
    const float* hg = d_H + t*Bb*DDEC;
#pragma unroll
    for (int q = 0; q < 32; q++){
        int i = tid + q*128;
        int b = i >> 7, k4 = i & 127;
        float4 v = *(const float4*)(hg + b*DDEC + k4*4);
        int col = (((b>>2) ^ (k4 & 7)) << 2) + (b & 3);
        hsm[(4*k4+0)*32 + col] = v.x;
        hsm[(4*k4+1)*32 + col] = v.y;
        hsm[(4*k4+2)*32 + col] = v.z;
        hsm[(4*k4+3)*32 + col] = v.w;
    }
    __syncthreads();

    int n = tid & 15;
    int bg = tid >> 4;
    U64F2 a01, a23, b01, b23;
    a01.u = 0ull; a23.u = 0ull; b01.u = 0ull; b23.u = 0ull;
#pragma unroll 4
    for (int k4 = 0; k4 < 128; k4++){
        int colg = ((bg ^ (k4 & 7)) << 2);
        const float* hrow = hsm + 4*k4*32 + colg;
        const float* wrow = Wsm + 4*k4*17 + n;
        F4U h0; h0.f = *(const float4*)(hrow);
        unsigned long long w0 = dup2(wrow[0]);
        fma2(a01.u, h0.u[0], w0); fma2(a23.u, h0.u[1], w0);
        F4U h1; h1.f = *(const float4*)(hrow + 32);
        unsigned long long w1 = dup2(wrow[17]);
        fma2(b01.u, h1.u[0], w1); fma2(b23.u, h1.u[1], w1);
        F4U h2; h2.f = *(const float4*)(hrow + 64);
        unsigned long long w2 = dup2(wrow[34]);
        fma2(a01.u, h2.u[0], w2); fma2(a23.u, h2.u[1], w2);
        F4U h3; h3.f = *(const float4*)(hrow + 96);
        unsigned long long w3 = dup2(wrow[51]);
        fma2(b01.u, h3.u[0], w3); fma2(b23.u, h3.u[1], w3);
    }
    {
        float4 o;
        o.x = a01.f.x + b01.f.x; o.y = a01.f.y + b01.f.y;
        o.z = a23.f.x + b23.f.x; o.w = a23.f.y + b23.f.y;
        *(float4*)&gsm[n*36 + bg*4] = o;
    }
    __syncthreads();

    int b = tid & 31, jj = tid >> 5;
    const float* xgp = d_XGd + (t*Bb + b)*(4*DDEC) + j0 + jj;
    float g0 = xgp[0]      + gsm[(0*4+jj)*36 + b];
    float g1 = xgp[DDEC]   + gsm[(1*4+jj)*36 + b];
    float g2 = xgp[2*DDEC] + gsm[(2*4+jj)*36 + b];
    float g3 = xgp[3*DDEC] + gsm[(3*4+jj)*36 + b];
    float cold = d_cd[(t&1)*Bb*DDEC + b*DDEC + j0 + jj];
    float i_ = sigm_f(g0), f_ = sigm_f(g1), gg = tanh_f(g2), o_ = sigm_f(g3);
    float cn = f_*cold + i_*gg;
    float hn = o_*tanh_f(cn);
    d_cd[((t+1)&1)*Bb*DDEC + b*DDEC + j0 + jj] = cn;
    d_H[(t+1)*Bb*DDEC + b*DDEC + j0 + jj] = hn;
}

// ---------------- small-M GEMM (ct path) ----------------
__global__ void __launch_bounds__(128) lstm_hgemm(
    const float* __restrict__ H0, const float* __restrict__ W0,
    float* __restrict__ part, int Ntot, int KH, int KS)
{
    int n0blk = blockIdx.x * 64;
    int ksub = KH / KS;
    int kbase = blockIdx.y * ksub;
    __shared__ float As[32][36];
    __shared__ float Ws[32][68];
    int tid = threadIdx.x;
    int bth = (tid >> 4) << 2;
    int nth = (tid & 15) << 2;
    float acc[4][4];
#pragma unroll
    for (int i=0;i<4;i++)
#pragma unroll
        for (int j=0;j<4;j++) acc[i][j] = 0.f;

    for (int k0 = 0; k0 < ksub; k0 += 32){
#pragma unroll
        for (int q=0;q<2;q++){
            int f4 = tid*2 + q;
            int bb = f4 >> 3, kq = (f4 & 7) << 2;
            float4 v = *(const float4*)(H0 + bb*KH + kbase + k0 + kq);
            As[kq+0][bb]=v.x; As[kq+1][bb]=v.y; As[kq+2][bb]=v.z; As[kq+3][bb]=v.w;
        }
#pragma unroll
        for (int q=0;q<4;q++){
            int f4 = tid*4 + q;
            int nn = f4 >> 3, kq = (f4 & 7) << 2;
            float4 v = *(const float4*)(W0 + (n0blk+nn)*KH + kbase + k0 + kq);
            Ws[kq+0][nn]=v.x; Ws[kq+1][nn]=v.y; Ws[kq+2][nn]=v.z; Ws[kq+3][nn]=v.w;
        }
        __syncthreads();
#pragma unroll
        for (int kk=0; kk<32; kk++){
            float4 a4 = *(const float4*)&As[kk][bth];
            float4 w4 = *(const float4*)&Ws[kk][nth];
            float aa[4] = {a4.x,a4.y,a4.z,a4.w};
            float ww[4] = {w4.x,w4.y,w4.z,w4.w};
#pragma unroll
            for (int i=0;i<4;i++)
#pragma unroll
                for (int j=0;j<4;j++) acc[i][j] += aa[i]*ww[j];
        }
        __syncthreads();
    }
    float* pbase = part + (blockIdx.y*32)*Ntot;
#pragma unroll
    for (int i=0;i<4;i++){
        float4 v; v.x=acc[i][0]; v.y=acc[i][1]; v.z=acc[i][2]; v.w=acc[i][3];
        *(float4*)&pbase[(bth+i)*Ntot + n0blk + nth] = v;
    }
}

// ---------------- misc glue ----------------
__global__ void mem_assemble(){
    int idx = blockIdx.x*256 + threadIdx.x;
    int b = idx >> 16, r = idx & 65535;
    int s = r >> 9, d = r & 511;
    float v;
    if (d < DENC) v = d_hf[((s+1)*Bb + b)*DENC + d];
    else          v = d_hb[((Ss - s)*Bb + b)*DENC + (d - DENC)];
    d_mem[idx] = v;
}
__global__ void ccat_build(){
    int idx = blockIdx.x*256 + threadIdx.x;
    int b = idx >> 9, j = idx & 511;
    d_ccat[idx] = (j < DENC) ? d_cf[b*DENC + j] : d_cb[b*DENC + (j - DENC)];
}
__global__ void ct_combine(){
    int idx = blockIdx.x*256 + threadIdx.x;
    int b = idx >> 9, j = idx & 511;
    float v = 0.f;
#pragma unroll
    for (int ky=0; ky<4; ky++) v += d_decpart[(ky*Bb + b)*DDEC + j];
    d_cd[b*DDEC + j] = lrelu_f(v);
}

// ---------------- attention ----------------
__global__ void __launch_bounds__(256) attn_kernel(){
    int b  = blockIdx.x;
    int t0 = blockIdx.y * 8;
    __shared__ float hs[8][512];
    __shared__ float sc[8][128];
    int tid = threadIdx.x;
    for (int i = tid; i < 8*512; i += 256){
        int tt = i >> 9, d = i & 511;
        hs[tt][d] = d_H[((t0 + tt + 1)*Bb + b)*DDEC + d];
    }
    __syncthreads();
    int w = tid >> 5, lane = tid & 31;
    const float scale = 0.04419417382415922f;
    for (int si = 0; si < 16; si++){
        int s = w*16 + si;
        const float* mrow = d_mem + (b*Ss + s)*DDEC;
        float acc[8] = {0,0,0,0,0,0,0,0};
#pragma unroll
        for (int q=0; q<4; q++){
            int d = q*128 + lane*4;
            float4 m4 = *(const float4*)(mrow + d);
#pragma unroll
            for (int tt=0; tt<8; tt++){
                float4 h4 = *(const float4*)&hs[tt][d];
                acc[tt] += m4.x*h4.x + m4.y*h4.y + m4.z*h4.z + m4.w*h4.w;
            }
        }
#pragma unroll
        for (int tt=0; tt<8; tt++){
            float v = acc[tt];
#pragma unroll
            for (int o=16;o>0;o>>=1) v += __shfl_xor_sync(0xffffffffu, v, o);
            if (lane == 0) sc[tt][s] = v * scale;
        }
    }
    __syncthreads();
    {
        int tt = w;
        float vals[4], m = -1e30f;
#pragma unroll
        for (int q=0;q<4;q++){ vals[q] = sc[tt][lane + q*32]; m = fmaxf(m, vals[q]); }
#pragma unroll
        for (int o=16;o>0;o>>=1) m = fmaxf(m, __shfl_xor_sync(0xffffffffu, m, o));
        float ssum = 0.f;
#pragma unroll
        for (int q=0;q<4;q++){ vals[q] = __expf(vals[q]-m); ssum += vals[q]; }
#pragma unroll
        for (int o=16;o>0;o>>=1) ssum += __shfl_xor_sync(0xffffffffu, ssum, o);
        float inv = 1.f/ssum;
#pragma unroll
        for (int q=0;q<4;q++) sc[tt][lane + q*32] = vals[q]*inv;
    }
    __syncthreads();
    {
        int d0 = tid*2;
        float acc[8][2];
#pragma unroll
        for (int tt=0;tt<8;tt++){ acc[tt][0]=0.f; acc[tt][1]=0.f; }
        for (int s=0; s<Ss; s++){
            float2 m2 = *(const float2*)(d_mem + (b*Ss + s)*DDEC + d0);
#pragma unroll
            for (int tt=0;tt<8;tt++){
                float p = sc[tt][s];
                acc[tt][0] += p*m2.x; acc[tt][1] += p*m2.y;
            }
        }
#pragma unroll
        for (int tt=0;tt<8;tt++){
            int rr = (t0+tt)*Bb + b;
            float2 v; v.x = acc[tt][0]; v.y = acc[tt][1];
            *(float2*)&d_FFN[rr*(2*DDEC) + DDEC + d0] = v;
        }
    }
    for (int i = tid; i < 8*512; i += 256){
        int tt = i >> 9, d = i & 511;
        int rr = (t0+tt)*Bb + b;
        d_FFN[rr*(2*DDEC) + d] = hs[tt][d];
    }
}

// ---------------- launcher ----------------
extern "C" void kernel_launch(void* const* d_in, const int* in_sizes, int n_in,
                              void* d_out, int out_size)
{
    const int*   inp        = (const int*)  d_in[0];
    const int*   label_i    = (const int*)  d_in[1];
    const int*   x          = (const int*)  d_in[2];
    const int*   label      = (const int*)  d_in[3];
    const float* start_emb  = (const float*)d_in[4];
    const float* tok_emb    = (const float*)d_in[5];
    const float* enc_style  = (const float*)d_in[6];
    const float* style_emb  = (const float*)d_in[7];
    const float* Wih_f      = (const float*)d_in[8];
    const float* Whh_f      = (const float*)d_in[9];
    const float* bih_f      = (const float*)d_in[10];
    const float* bhh_f      = (const float*)d_in[11];
    const float* Wih_b      = (const float*)d_in[12];
    const float* Whh_b      = (const float*)d_in[13];
    const float* bih_b      = (const float*)d_in[14];
    const float* bhh_b      = (const float*)d_in[15];
    const float* Wih_d      = (const float*)d_in[16];
    const float* Whh_d      = (const float*)d_in[17];
    const float* bih_d      = (const float*)d_in[18];
    const float* bhh_d      = (const float*)d_in[19];
    const float* W_tr       = (const float*)d_in[20];
    const float* W_f1       = (const float*)d_in[21];
    const float* b_f1       = (const float*)d_in[22];
    const float* W_f2       = (const float*)d_in[23];
    float* out = (float*)d_out;

    float *embS, *decin, *XGf, *XGb, *XGd, *ccat, *decpart, *FFN, *HID;
    __half *Wf16, *HIDH;
    cudaGetSymbolAddress((void**)&embS,   d_embS);
    cudaGetSymbolAddress((void**)&decin,  d_decin);
    cudaGetSymbolAddress((void**)&XGf,    d_XGf);
    cudaGetSymbolAddress((void**)&XGb,    d_XGb);
    cudaGetSymbolAddress((void**)&XGd,    d_XGd);
    cudaGetSymbolAddress((void**)&ccat,   d_ccat);
    cudaGetSymbolAddress((void**)&decpart,d_decpart);
    cudaGetSymbolAddress((void**)&FFN,    d_FFN);
    cudaGetSymbolAddress((void**)&HID,    d_HID);
    cudaGetSymbolAddress((void**)&Wf16,   d_Wf16);
    cudaGetSymbolAddress((void**)&HIDH,   d_HIDH);

    cudaFuncSetAttribute(f2_mma,   cudaFuncAttributeMaxDynamicSharedMemorySize, F2_SMEM);
    cudaFuncSetAttribute(enc_step, cudaFuncAttributeMaxDynamicSharedMemorySize, ENC2_SMEM);
    cudaFuncSetAttribute(dec_step, cudaFuncAttributeMaxDynamicSharedMemorySize, DEC2_SMEM);

    // prep
    p_emb  <<<2048,256>>>(inp, tok_emb);
    p_decin<<<2048,256>>>(x, tok_emb, start_emb);
    p_init <<<192,256>>>(label_i, label, enc_style, style_emb);
    conv_w16<<<64000,256>>>(W_f2, Wf16, Vv*DDEC);

    // batched x-part of all LSTM gates (biases folded in)
    gemm_nt<<<dim3( 8,32),256>>>(embS,  Wih_f, XGf, 4096,1024, 128, bih_f, bhh_f, 0,0);
    gemm_nt<<<dim3( 8,32),256>>>(embS,  Wih_b, XGb, 4096,1024, 128, bih_b, bhh_b, 0,1);
    gemm_nt<<<dim3(16,32),256>>>(decin, Wih_d, XGd, 4096,2048, 128, bih_d, bhh_d, 0,0);

    // encoder recurrence: ONE fused kernel per step (full-K, self-contained cell)
    for (int t = 0; t < Ss; t++)
        enc_step<<<dim3(64,2),128,ENC2_SMEM>>>(Whh_f, Whh_b, t);
    mem_assemble<<<8192,256>>>();

    // c_t = lrelu(concat(cf,cb) @ W_tr^T)
    ccat_build<<<64,256>>>();
    lstm_hgemm<<<dim3(8,4),128>>>(ccat, W_tr, decpart, DDEC, DDEC, 4);
    ct_combine<<<64,256>>>();

    // decoder recurrence: ONE fused kernel per step
    for (int t = 0; t < Tt; t++)
        dec_step<<<128,128,DEC2_SMEM>>>(Whh_d, t);

    // batched attention -> FFN input
    attn_kernel<<<dim3(32,16),256>>>();

    // F1: lrelu(FFN @ W_f1^T + b_f1)
    gemm_nt<<<dim3(4,32),256>>>(FFN, W_f1, HID, 4096, 512, 1024, b_f1, nullptr, 1,0);
    conv_w16<<<8192,256>>>(HID, HIDH, Tt*Bb*DDEC);

    // F2 on tensor cores: single-pass fp16, remapped to [B,T,V]
    f2_mma<<<dim3(32,125), 256, F2_SMEM>>>(HIDH, Wf16, out);
}

// round 14
// speedup vs baseline: 1.5442x; 1.2866x over previous
#include <cuda_runtime.h>
#include <cuda_bf16.h>
#include <cuda_fp16.h>
#include <cstdint>

#define Bb 32
#define Ss 128
#define Tt 128
#define DEMB 128
#define DENC 256
#define DDEC 512
#define Vv 32000

// ---------------- scratch (device globals; no runtime allocation) ----------------
__device__ float d_embS [Ss*Bb*DEMB];
__device__ float d_decin[Tt*Bb*DEMB];
__device__ float d_XGf  [Ss*Bb*4*DENC];
__device__ float d_XGb  [Ss*Bb*4*DENC];
__device__ float d_XGd  [Tt*Bb*4*DDEC];
__device__ float d_hf   [(Ss+1)*Bb*DENC];
__device__ float d_hb   [(Ss+1)*Bb*DENC];
__device__ float d_cf   [2*Bb*DENC];
__device__ float d_cb   [2*Bb*DENC];
__device__ float d_encpart[2*4*Bb*4*DENC];     // [dir][ks(4)][b][1024]
__device__ float d_mem  [Bb*Ss*2*DENC];
__device__ float d_ccat [Bb*2*DENC];
__device__ float d_H    [(Tt+1)*Bb*DDEC];
__device__ float d_cd   [2*Bb*DDEC];
__device__ float d_decpart[8*Bb*4*DDEC];       // [ks(8)][b][2048]; also reused by ct path
__device__ float d_FFN  [Tt*Bb*2*DDEC];
__device__ float d_HID  [Tt*Bb*DDEC];
// fp16 operands for tensor-core F2
__device__ __half d_Wf16 [Vv*DDEC];
__device__ __half d_HIDH [Tt*Bb*DDEC];

// ---------------- helpers ----------------
__device__ __forceinline__ float lrelu_f(float x){ return x >= 0.f ? x : 0.1f*x; }
__device__ __forceinline__ float sigm_f (float x){ return 1.f/(1.f+__expf(-x)); }
__device__ __forceinline__ float tanh_f (float x){
    float ax = fabsf(x);
    float e  = __expf(-2.f*ax);
    float r  = (1.f-e)/(1.f+e);
    return x >= 0.f ? r : -r;
}
__device__ __forceinline__ unsigned long long dup2(float a){
    unsigned long long r;
    asm("mov.b64 %0, {%1, %1};" : "=l"(r) : "f"(a));
    return r;
}
__device__ __forceinline__ void fma2(unsigned long long &c, unsigned long long a, unsigned long long w){
    asm("fma.rn.f32x2 %0, %1, %2, %0;" : "+l"(c) : "l"(a), "l"(w));
}
union F4U { float4 f; unsigned long long u[2]; };
union U64F2 { unsigned long long u; float2 f; };

__device__ __forceinline__ uint32_t smem_u32(const void* p){
    uint32_t a; asm("{ .reg .u64 t; cvta.to.shared.u64 t, %1; cvt.u32.u64 %0, t; }" : "=r"(a) : "l"(p));
    return a;
}
__device__ __forceinline__ void cp16(uint32_t saddr, const void* gaddr){
    asm volatile("cp.async.cg.shared.global [%0], [%1], 16;" :: "r"(saddr), "l"(gaddr));
}
__device__ __forceinline__ void ldm_x4(uint32_t addr, uint32_t &r0, uint32_t &r1, uint32_t &r2, uint32_t &r3){
    asm volatile("ldmatrix.sync.aligned.m8n8.x4.shared.b16 {%0,%1,%2,%3}, [%4];"
                 : "=r"(r0), "=r"(r1), "=r"(r2), "=r"(r3) : "r"(addr));
}
__device__ __forceinline__ void mma16816h(float* c, uint32_t a0, uint32_t a1, uint32_t a2, uint32_t a3,
                                          uint32_t b0, uint32_t b1){
    asm volatile("mma.sync.aligned.m16n8k16.row.col.f32.f16.f16.f32 "
                 "{%0,%1,%2,%3}, {%4,%5,%6,%7}, {%8,%9}, {%0,%1,%2,%3};"
                 : "+f"(c[0]), "+f"(c[1]), "+f"(c[2]), "+f"(c[3])
                 : "r"(a0), "r"(a1), "r"(a2), "r"(a3), "r"(b0), "r"(b1));
}

// ---------------- prep kernels ----------------
__global__ void p_emb(const int* __restrict__ inp, const float* __restrict__ tok_emb){
    int idx = blockIdx.x*256 + threadIdx.x;
    int sb = idx >> 7, d = idx & 127;
    int s = sb >> 5, b = sb & 31;
    d_embS[idx] = tok_emb[inp[b*Ss + s]*DEMB + d];
}
__global__ void p_decin(const int* __restrict__ x, const float* __restrict__ tok_emb,
                        const float* __restrict__ start_emb){
    int idx = blockIdx.x*256 + threadIdx.x;
    int tb = idx >> 7, d = idx & 127;
    int t = tb >> 5, b = tb & 31;
    d_decin[idx] = (t == 0) ? start_emb[d] : tok_emb[x[b*Tt + (t-1)]*DEMB + d];
}
__global__ void p_init(const int* __restrict__ label_i, const int* __restrict__ label,
                       const float* __restrict__ enc_style_emb, const float* __restrict__ style_emb){
    int idx = blockIdx.x*256 + threadIdx.x;
    if (idx < 16384){
        int dir = idx >> 13, r = idx & 8191;
        int b = r >> 8, j = r & 255;
        float v = enc_style_emb[label_i[b]*(2*DENC) + dir*DENC + j];
        (dir ? d_hb : d_hf)[b*DENC + j] = v;
    } else if (idx < 32768){
        int r = idx - 16384;
        int dir = r >> 13; r &= 8191;
        (dir ? d_cb : d_cf)[r] = 0.f;
    } else {
        int r = idx - 32768;
        int b = r >> 9, j = r & 511;
        d_H[b*DDEC + j] = style_emb[label[b]*DDEC + j];
    }
}
__global__ void conv_w16(const float* __restrict__ src, __half* __restrict__ dst, int n){
    int i = blockIdx.x*256 + threadIdx.x;
    if (i < n) dst[i] = __float2half_rn(src[i]);
}

// ---------------- fp32 GEMM (XG / F1): C = A @ W^T ----------------
__global__ void __launch_bounds__(256) gemm_nt(
    const float* __restrict__ A, const float* __restrict__ W, float* __restrict__ C,
    int M, int N, int K,
    const float* __restrict__ bias1, const float* __restrict__ bias2,
    int act, int remapA)
{
    __shared__ float As[8][128];
    __shared__ float Bs[8][128];
    int tid = threadIdx.x;
    int bm = blockIdx.y * 128, bn = blockIdx.x * 128;
    int lr = tid >> 1;
    int lc = (tid & 1) << 2;
    int arow = bm + lr;
    if (remapA) arow = ((Ss-1 - (arow >> 5)) << 5) | (arow & 31);
    const float* Aptr = A + arow*K + lc;
    const float* Wptr = W + (bn + lr)*K + lc;

    int m0 = (tid >> 4) << 3;
    int n0 = (tid & 15) << 3;
    unsigned long long acc[8][4];
#pragma unroll
    for (int i=0;i<8;i++)
#pragma unroll
        for (int j=0;j<4;j++) acc[i][j] = 0ull;

    for (int k0 = 0; k0 < K; k0 += 8){
        float4 a4 = *(const float4*)(Aptr + k0);
        float4 w4 = *(const float4*)(Wptr + k0);
        As[lc+0][lr]=a4.x; As[lc+1][lr]=a4.y; As[lc+2][lr]=a4.z; As[lc+3][lr]=a4.w;
        Bs[lc+0][lr]=w4.x; Bs[lc+1][lr]=w4.y; Bs[lc+2][lr]=w4.z; Bs[lc+3][lr]=w4.w;
        __syncthreads();
#pragma unroll
        for (int kk=0; kk<8; kk++){
            float4 a0 = *(const float4*)&As[kk][m0];
            float4 a1 = *(const float4*)&As[kk][m0+4];
            F4U ub0, ub1;
            ub0.f = *(const float4*)&Bs[kk][n0];
            ub1.f = *(const float4*)&Bs[kk][n0+4];
            unsigned long long w0=ub0.u[0], w1=ub0.u[1], w2=ub1.u[0], w3=ub1.u[1];
            float av[8] = {a0.x,a0.y,a0.z,a0.w,a1.x,a1.y,a1.z,a1.w};
#pragma unroll
            for (int i=0;i<8;i++){
                unsigned long long ad = dup2(av[i]);
                fma2(acc[i][0], ad, w0);
                fma2(acc[i][1], ad, w1);
                fma2(acc[i][2], ad, w2);
                fma2(acc[i][3], ad, w3);
            }
        }
        __syncthreads();
    }
#pragma unroll
    for (int i=0;i<8;i++){
        int mg = bm + m0 + i;
#pragma unroll
        for (int j=0;j<4;j++){
            U64F2 u; u.u = acc[i][j];
            float2 v = u.f;
            int ng = bn + n0 + 2*j;
            if (bias1){ v.x += bias1[ng]; v.y += bias1[ng+1]; }
            if (bias2){ v.x += bias2[ng]; v.y += bias2[ng+1]; }
            if (act){ v.x = lrelu_f(v.x); v.y = lrelu_f(v.y); }
            *(float2*)&C[mg*N + ng] = v;
        }
    }
}

// ---------------- mma.sync fp16 single-pass F2 GEMM ----------------
#define F2_NCHUNK 16
#define F2_ASTG   (128*40*2)
#define F2_BSTG   (256*40*2)
#define F2_STG    (F2_ASTG + F2_BSTG)
#define F2_SMEM   (3*F2_STG)
__global__ void __launch_bounds__(256) f2_mma(
    const __half* __restrict__ AH, const __half* __restrict__ Bg, float* __restrict__ out)
{
    extern __shared__ __half sm[];
    int tid = threadIdx.x;
    int wid = tid >> 5, lane = tid & 31;
    int warp_m = wid & 1, warp_n = wid >> 1;
    int bm = blockIdx.x * 128;
    int bn = blockIdx.y * 256;
    uint32_t sbase = smem_u32(sm);

    float acc[4][8][4];
#pragma unroll
    for (int i=0;i<4;i++)
#pragma unroll
        for (int j=0;j<8;j++)
#pragma unroll
            for (int q=0;q<4;q++) acc[i][j][q] = 0.f;

    auto load_chunk = [&](int c, int s){
        int k0 = c * 32;
        uint32_t base = sbase + (uint32_t)s * F2_STG;
#pragma unroll
        for (int q=0; q<2; q++){
            int i = q*256 + tid;
            int row = i >> 2, sg = i & 3;
            cp16(base + (uint32_t)(row*80 + sg*16), AH + (size_t)(bm + row)*DDEC + k0 + sg*8);
        }
#pragma unroll
        for (int q=0; q<4; q++){
            int i = q*256 + tid;
            int row = i >> 2, sg = i & 3;
            cp16(base + F2_ASTG + (uint32_t)(row*80 + sg*16),
                 Bg + (size_t)(bn + row)*DDEC + k0 + sg*8);
        }
        asm volatile("cp.async.commit_group;" ::: "memory");
    };

    load_chunk(0, 0);
    load_chunk(1, 1);

    int ld_s = 2, cs = 0;
    for (int c = 0; c < F2_NCHUNK; c++){
        if (c < F2_NCHUNK-1) asm volatile("cp.async.wait_group 1;" ::: "memory");
        else                 asm volatile("cp.async.wait_group 0;" ::: "memory");
        __syncthreads();
        if (c + 2 < F2_NCHUNK){
            load_chunk(c+2, ld_s);
            ld_s++; if (ld_s == 3) ld_s = 0;
        }
        uint32_t baseA = sbase + (uint32_t)cs * F2_STG;
        uint32_t baseB = baseA + F2_ASTG;
#pragma unroll
        for (int ks = 0; ks < 2; ks++){
            int kc = ks * 16;
            int g = lane >> 3, r = lane & 7;
            uint32_t af[4][4];
#pragma unroll
            for (int mt=0; mt<4; mt++){
                int row = warp_m*64 + mt*16 + (g & 1)*8 + r;
                int col = kc + (g >> 1)*8;
                ldm_x4(baseA + (uint32_t)(row*80 + col*2), af[mt][0], af[mt][1], af[mt][2], af[mt][3]);
            }
            uint32_t bf[8][2];
#pragma unroll
            for (int j=0; j<4; j++){
                int nrow = warp_n*64 + (j*2 + (g >> 1))*8 + r;
                int col = kc + (g & 1)*8;
                ldm_x4(baseB + (uint32_t)(nrow*80 + col*2),
                       bf[j*2][0], bf[j*2][1], bf[j*2+1][0], bf[j*2+1][1]);
            }
#pragma unroll
            for (int mt=0; mt<4; mt++)
#pragma unroll
                for (int nt=0; nt<8; nt++)
                    mma16816h(acc[mt][nt], af[mt][0], af[mt][1], af[mt][2], af[mt][3],
                              bf[nt][0], bf[nt][1]);
        }
        __syncthreads();
        cs++; if (cs == 3) cs = 0;
    }

#pragma unroll
    for (int mt=0; mt<4; mt++){
#pragma unroll
        for (int half=0; half<2; half++){
            int mg = bm + warp_m*64 + mt*16 + (lane >> 2) + half*8;
            int t = mg >> 5, b = mg & 31;
            float* dst = out + (size_t)(b*Tt + t)*Vv + bn + warp_n*64;
#pragma unroll
            for (int nt=0; nt<8; nt++){
                float2 v;
                v.x = acc[mt][nt][half*2+0];
                v.y = acc[mt][nt][half*2+1];
                *(float2*)&dst[nt*8 + 2*(lane & 3)] = v;
            }
        }
    }
}

// ---------------- small-M recurrence GEMM (f32x2-packed inner loop) ----------------
__global__ void __launch_bounds__(128) lstm_hgemm(
    const float* __restrict__ H0, const float* __restrict__ H1,
    const float* __restrict__ W0, const float* __restrict__ W1,
    float* __restrict__ part, int Ntot, int KH, int KS)
{
    int dir = blockIdx.z;
    const float* Hd = dir ? H1 : H0;
    const float* Wd = dir ? W1 : W0;
    int n0blk = blockIdx.x * 64;
    int ksub = KH / KS;
    int kbase = blockIdx.y * ksub;
    __shared__ float As[32][36];
    __shared__ float Ws[32][68];
    int tid = threadIdx.x;
    int bth = (tid >> 4) << 2;
    int nth = (tid & 15) << 2;
    unsigned long long accp[2][4];     // [b-pair][n], packed over 2 consecutive b
#pragma unroll
    for (int p=0;p<2;p++)
#pragma unroll
        for (int j=0;j<4;j++) accp[p][j] = 0ull;

    for (int k0 = 0; k0 < ksub; k0 += 32){
#pragma unroll
        for (int q=0;q<2;q++){
            int f4 = tid*2 + q;
            int bb = f4 >> 3, kq = (f4 & 7) << 2;
            float4 v = *(const float4*)(Hd + bb*KH + kbase + k0 + kq);
            As[kq+0][bb]=v.x; As[kq+1][bb]=v.y; As[kq+2][bb]=v.z; As[kq+3][bb]=v.w;
        }
#pragma unroll
        for (int q=0;q<4;q++){
            int f4 = tid*4 + q;
            int nn = f4 >> 3, kq = (f4 & 7) << 2;
            float4 v = *(const float4*)(Wd + (n0blk+nn)*KH + kbase + k0 + kq);
            Ws[kq+0][nn]=v.x; Ws[kq+1][nn]=v.y; Ws[kq+2][nn]=v.z; Ws[kq+3][nn]=v.w;
        }
        __syncthreads();
#pragma unroll
        for (int kk=0; kk<32; kk++){
            F4U a4; a4.f = *(const float4*)&As[kk][bth];
            float4 w4 = *(const float4*)&Ws[kk][nth];
            unsigned long long wd0 = dup2(w4.x);
            unsigned long long wd1 = dup2(w4.y);
            unsigned long long wd2 = dup2(w4.z);
            unsigned long long wd3 = dup2(w4.w);
            fma2(accp[0][0], a4.u[0], wd0);
            fma2(accp[0][1], a4.u[0], wd1);
            fma2(accp[0][2], a4.u[0], wd2);
            fma2(accp[0][3], a4.u[0], wd3);
            fma2(accp[1][0], a4.u[1], wd0);
            fma2(accp[1][1], a4.u[1], wd1);
            fma2(accp[1][2], a4.u[1], wd2);
            fma2(accp[1][3], a4.u[1], wd3);
        }
        __syncthreads();
    }
    float* pbase = part + ((dir*KS + blockIdx.y)*32)*Ntot;
#pragma unroll
    for (int p=0;p<2;p++){
        U64F2 c0,c1,c2,c3;
        c0.u=accp[p][0]; c1.u=accp[p][1]; c2.u=accp[p][2]; c3.u=accp[p][3];
        float4 vlo; vlo.x=c0.f.x; vlo.y=c1.f.x; vlo.z=c2.f.x; vlo.w=c3.f.x;
        float4 vhi; vhi.x=c0.f.y; vhi.y=c1.f.y; vhi.z=c2.f.y; vhi.w=c3.f.y;
        *(float4*)&pbase[(bth+2*p+0)*Ntot + n0blk + nth] = vlo;
        *(float4*)&pbase[(bth+2*p+1)*Ntot + n0blk + nth] = vhi;
    }
}

// ---------------- cell updates ----------------
__global__ void enc_cell(int t){
    int idx = blockIdx.x*256 + threadIdx.x;
    int dir = idx >> 13, r = idx & 8191;
    int b = r >> 8, j = r & 255;
    const float* XG = dir ? d_XGb : d_XGf;
    float g[4];
#pragma unroll
    for (int gt=0; gt<4; gt++){
        int n = gt*DENC + j;
        float v = XG[(t*Bb + b)*(4*DENC) + n];
#pragma unroll
        for (int ks=0; ks<4; ks++)
            v += d_encpart[((dir*4+ks)*Bb + b)*(4*DENC) + n];
        g[gt] = v;
    }
    float* cbuf = dir ? d_cb : d_cf;
    float cold = cbuf[(t&1)*Bb*DENC + b*DENC + j];
    float i_ = sigm_f(g[0]), f_ = sigm_f(g[1]), gg = tanh_f(g[2]), o_ = sigm_f(g[3]);
    float cn = f_*cold + i_*gg;
    float hn = o_*tanh_f(cn);
    cbuf[((t+1)&1)*Bb*DENC + b*DENC + j] = cn;
    (dir ? d_hb : d_hf)[((t+1)*Bb + b)*DENC + j] = hn;
}
__global__ void dec_cell(int t){
    int idx = blockIdx.x*256 + threadIdx.x;
    int b = idx >> 9, j = idx & 511;
    float g[4];
#pragma unroll
    for (int gt=0; gt<4; gt++){
        int n = gt*DDEC + j;
        float v = d_XGd[(t*Bb + b)*(4*DDEC) + n];
#pragma unroll
        for (int ky=0; ky<8; ky++) v += d_decpart[(ky*Bb + b)*(4*DDEC) + n];
        g[gt] = v;
    }
    float cold = d_cd[(t&1)*Bb*DDEC + b*DDEC + j];
    float i_ = sigm_f(g[0]), f_ = sigm_f(g[1]), gg = tanh_f(g[2]), o_ = sigm_f(g[3]);
    float cn = f_*cold + i_*gg;
    float hn = o_*tanh_f(cn);
    d_cd[((t+1)&1)*Bb*DDEC + b*DDEC + j] = cn;
    d_H[((t+1)*Bb + b)*DDEC + j] = hn;
}

// ---------------- misc glue ----------------
__global__ void mem_assemble(){
    int idx = blockIdx.x*256 + threadIdx.x;
    int b = idx >> 16, r = idx & 65535;
    int s = r >> 9, d = r & 511;
    float v;
    if (d < DENC) v = d_hf[((s+1)*Bb + b)*DENC + d];
    else          v = d_hb[((Ss - s)*Bb + b)*DENC + (d - DENC)];
    d_mem[idx] = v;
}
__global__ void ccat_build(){
    int idx = blockIdx.x*256 + threadIdx.x;
    int b = idx >> 9, j = idx & 511;
    d_ccat[idx] = (j < DENC) ? d_cf[b*DENC + j] : d_cb[b*DENC + (j - DENC)];
}
__global__ void ct_combine(){
    int idx = blockIdx.x*256 + threadIdx.x;
    int b = idx >> 9, j = idx & 511;
    float v = 0.f;
#pragma unroll
    for (int ky=0; ky<4; ky++) v += d_decpart[(ky*Bb + b)*DDEC + j];
    d_cd[b*DDEC + j] = lrelu_f(v);
}

// ---------------- attention ----------------
__global__ void __launch_bounds__(256) attn_kernel(){
    int b  = blockIdx.x;
    int t0 = blockIdx.y * 8;
    __shared__ float hs[8][512];
    __shared__ float sc[8][128];
    int tid = threadIdx.x;
    for (int i = tid; i < 8*512; i += 256){
        int tt = i >> 9, d = i & 511;
        hs[tt][d] = d_H[((t0 + tt + 1)*Bb + b)*DDEC + d];
    }
    __syncthreads();
    int w = tid >> 5, lane = tid & 31;
    const float scale = 0.04419417382415922f;
    for (int si = 0; si < 16; si++){
        int s = w*16 + si;
        const float* mrow = d_mem + (b*Ss + s)*DDEC;
        float acc[8] = {0,0,0,0,0,0,0,0};
#pragma unroll
        for (int q=0; q<4; q++){
            int d = q*128 + lane*4;
            float4 m4 = *(const float4*)(mrow + d);
#pragma unroll
            for (int tt=0; tt<8; tt++){
                float4 h4 = *(const float4*)&hs[tt][d];
                acc[tt] += m4.x*h4.x + m4.y*h4.y + m4.z*h4.z + m4.w*h4.w;
            }
        }
#pragma unroll
        for (int tt=0; tt<8; tt++){
            float v = acc[tt];
#pragma unroll
            for (int o=16;o>0;o>>=1) v += __shfl_xor_sync(0xffffffffu, v, o);
            if (lane == 0) sc[tt][s] = v * scale;
        }
    }
    __syncthreads();
    {
        int tt = w;
        float vals[4], m = -1e30f;
#pragma unroll
        for (int q=0;q<4;q++){ vals[q] = sc[tt][lane + q*32]; m = fmaxf(m, vals[q]); }
#pragma unroll
        for (int o=16;o>0;o>>=1) m = fmaxf(m, __shfl_xor_sync(0xffffffffu, m, o));
        float ssum = 0.f;
#pragma unroll
        for (int q=0;q<4;q++){ vals[q] = __expf(vals[q]-m); ssum += vals[q]; }
#pragma unroll
        for (int o=16;o>0;o>>=1) ssum += __shfl_xor_sync(0xffffffffu, ssum, o);
        float inv = 1.f/ssum;
#pragma unroll
        for (int q=0;q<4;q++) sc[tt][lane + q*32] = vals[q]*inv;
    }
    __syncthreads();
    {
        int d0 = tid*2;
        float acc[8][2];
#pragma unroll
        for (int tt=0;tt<8;tt++){ acc[tt][0]=0.f; acc[tt][1]=0.f; }
        for (int s=0; s<Ss; s++){
            float2 m2 = *(const float2*)(d_mem + (b*Ss + s)*DDEC + d0);
#pragma unroll
            for (int tt=0;tt<8;tt++){
                float p = sc[tt][s];
                acc[tt][0] += p*m2.x; acc[tt][1] += p*m2.y;
            }
        }
#pragma unroll
        for (int tt=0;tt<8;tt++){
            int rr = (t0+tt)*Bb + b;
            float2 v; v.x = acc[tt][0]; v.y = acc[tt][1];
            *(float2*)&d_FFN[rr*(2*DDEC) + DDEC + d0] = v;
        }
    }
    for (int i = tid; i < 8*512; i += 256){
        int tt = i >> 9, d = i & 511;
        int rr = (t0+tt)*Bb + b;
        d_FFN[rr*(2*DDEC) + d] = hs[tt][d];
    }
}

// ---------------- launcher ----------------
extern "C" void kernel_launch(void* const* d_in, const int* in_sizes, int n_in,
                              void* d_out, int out_size)
{
    const int*   inp        = (const int*)  d_in[0];
    const int*   label_i    = (const int*)  d_in[1];
    const int*   x          = (const int*)  d_in[2];
    const int*   label      = (const int*)  d_in[3];
    const float* start_emb  = (const float*)d_in[4];
    const float* tok_emb    = (const float*)d_in[5];
    const float* enc_style  = (const float*)d_in[6];
    const float* style_emb  = (const float*)d_in[7];
    const float* Wih_f      = (const float*)d_in[8];
    const float* Whh_f      = (const float*)d_in[9];
    const float* bih_f      = (const float*)d_in[10];
    const float* bhh_f      = (const float*)d_in[11];
    const float* Wih_b      = (const float*)d_in[12];
    const float* Whh_b      = (const float*)d_in[13];
    const float* bih_b      = (const float*)d_in[14];
    const float* bhh_b      = (const float*)d_in[15];
    const float* Wih_d      = (const float*)d_in[16];
    const float* Whh_d      = (const float*)d_in[17];
    const float* bih_d      = (const float*)d_in[18];
    const float* bhh_d      = (const float*)d_in[19];
    const float* W_tr       = (const float*)d_in[20];
    const float* W_f1       = (const float*)d_in[21];
    const float* b_f1       = (const float*)d_in[22];
    const float* W_f2       = (const float*)d_in[23];
    float* out = (float*)d_out;

    float *embS, *decin, *XGf, *XGb, *XGd, *hf, *hb, *H, *ccat, *decpart, *encpart, *FFN, *HID;
    __half *Wf16, *HIDH;
    cudaGetSymbolAddress((void**)&embS,   d_embS);
    cudaGetSymbolAddress((void**)&decin,  d_decin);
    cudaGetSymbolAddress((void**)&XGf,    d_XGf);
    cudaGetSymbolAddress((void**)&XGb,    d_XGb);
    cudaGetSymbolAddress((void**)&XGd,    d_XGd);
    cudaGetSymbolAddress((void**)&hf,     d_hf);
    cudaGetSymbolAddress((void**)&hb,     d_hb);
    cudaGetSymbolAddress((void**)&H,      d_H);
    cudaGetSymbolAddress((void**)&ccat,   d_ccat);
    cudaGetSymbolAddress((void**)&decpart,d_decpart);
    cudaGetSymbolAddress((void**)&encpart,d_encpart);
    cudaGetSymbolAddress((void**)&FFN,    d_FFN);
    cudaGetSymbolAddress((void**)&HID,    d_HID);
    cudaGetSymbolAddress((void**)&Wf16,   d_Wf16);
    cudaGetSymbolAddress((void**)&HIDH,   d_HIDH);

    cudaFuncSetAttribute(f2_mma, cudaFuncAttributeMaxDynamicSharedMemorySize, F2_SMEM);

    // prep
    p_emb  <<<2048,256>>>(inp, tok_emb);
    p_decin<<<2048,256>>>(x, tok_emb, start_emb);
    p_init <<<192,256>>>(label_i, label, enc_style, style_emb);
    conv_w16<<<64000,256>>>(W_f2, Wf16, Vv*DDEC);

    // batched x-part of all LSTM gates (biases folded in)
    gemm_nt<<<dim3( 8,32),256>>>(embS,  Wih_f, XGf, 4096,1024, 128, bih_f, bhh_f, 0,0);
    gemm_nt<<<dim3( 8,32),256>>>(embS,  Wih_b, XGb, 4096,1024, 128, bih_b, bhh_b, 0,1);
    gemm_nt<<<dim3(16,32),256>>>(decin, Wih_d, XGd, 4096,2048, 128, bih_d, bhh_d, 0,0);

    // encoder recurrence (fwd + bwd fused per step), K-split x4
    for (int t = 0; t < Ss; t++){
        lstm_hgemm<<<dim3(16,4,2),128>>>(hf + t*Bb*DENC, hb + t*Bb*DENC,
                                         Whh_f, Whh_b, encpart, 4*DENC, DENC, 4);
        enc_cell<<<64,256>>>(t);
    }
    mem_assemble<<<8192,256>>>();

    // c_t = lrelu(concat(cf,cb) @ W_tr^T)
    ccat_build<<<64,256>>>();
    lstm_hgemm<<<dim3(8,4,1),128>>>(ccat, nullptr, W_tr, nullptr, decpart, DDEC, DDEC, 4);
    ct_combine<<<64,256>>>();

    // decoder recurrence, K-split x8
    for (int t = 0; t < Tt; t++){
        lstm_hgemm<<<dim3(32,8,1),128>>>(H + t*Bb*DDEC, nullptr,
                                         Whh_d, nullptr, decpart, 4*DDEC, DDEC, 8);
        dec_cell<<<64,256>>>(t);
    }

    // batched attention -> FFN input
    attn_kernel<<<dim3(32,16),256>>>();

    // F1: lrelu(FFN @ W_f1^T + b_f1)
    gemm_nt<<<dim3(4,32),256>>>(FFN, W_f1, HID, 4096, 512, 1024, b_f1, nullptr, 1,0);
    conv_w16<<<8192,256>>>(HID, HIDH, Tt*Bb*DDEC);

    // F2 on tensor cores: single-pass fp16, remapped to [B,T,V]
    f2_mma<<<dim3(32,125), 256, F2_SMEM>>>(HIDH, Wf16, out);
}